// round 10
// baseline (speedup 1.0000x reference)
#include <cuda_runtime.h>
#include <math.h>
#include <stdint.h>

// ---------------- problem constants ----------------
#define N_ATOMS    100000
#define N_BONDS_DIR 200000
#define N_BONDS    100000
#define N_ANGLES   400000
#define N_GRAPHS   2048
#define D          128
#define H          256
#define N_BCENT    20
#define N_ACENT    32
#define GAMMA      10.0f
#define LN_EPS     1e-5f

// ---------------- device scratch (allocation-free) ----------------
__device__ float g_agg[N_ATOMS * D];
__device__ float g_bond_embed[N_BONDS * D];
__device__ float g_agg_e[N_BONDS * N_ACENT];
__device__ float g_acnt[N_BONDS];
__device__ float g_counts_a[N_GRAPHS];
__device__ float g_counts_b[N_GRAPHS];

// ---------------- zero kernels ----------------
__global__ void zero_agg_kernel() {
    int i = blockIdx.x * blockDim.x + threadIdx.x;
    float4* p = reinterpret_cast<float4*>(g_agg);
    int n4 = (N_ATOMS * D) / 4;
    if (i < n4) p[i] = make_float4(0.f, 0.f, 0.f, 0.f);
}

__global__ void zero_e_kernel() {
    int i = blockIdx.x * blockDim.x + threadIdx.x;
    int n4 = (N_BONDS * N_ACENT) / 4;
    if (i < n4) reinterpret_cast<float4*>(g_agg_e)[i] = make_float4(0.f, 0.f, 0.f, 0.f);
    if (i < N_BONDS) g_acnt[i] = 0.f;
}

__global__ void zero_counts_kernel() {
    int i = blockIdx.x * blockDim.x + threadIdx.x;
    if (i < N_GRAPHS) { g_counts_a[i] = 0.f; g_counts_b[i] = 0.f; }
}

__global__ void count_kernel(const int* __restrict__ ab_gid, const int* __restrict__ ba_gid) {
    int i = blockIdx.x * blockDim.x + threadIdx.x;
    if (i < N_ATOMS) atomicAdd(&g_counts_a[ab_gid[i]], 1.f);
    if (i < N_BONDS) atomicAdd(&g_counts_b[ba_gid[i]], 1.f);
}

// ---------------- atom-bond scatter ----------------
__global__ void scatter_ab_kernel(const float* __restrict__ nf, const float* __restrict__ ef,
                                  const int* __restrict__ src, const int* __restrict__ dst) {
    int idx  = blockIdx.x * blockDim.x + threadIdx.x;
    int e    = idx >> 5;
    int lane = idx & 31;
    if (e >= N_BONDS_DIR) return;
    int s = src[e];
    int d = dst[e];
    float4 m = reinterpret_cast<const float4*>(nf)[(size_t)s * 32 + lane];
    float4 v = reinterpret_cast<const float4*>(ef)[(size_t)e * 32 + lane];
    m.x += v.x; m.y += v.y; m.z += v.z; m.w += v.w;
    float* p = &g_agg[(size_t)d * D + lane * 4];
    atomicAdd(p + 0, m.x);
    atomicAdd(p + 1, m.y);
    atomicAdd(p + 2, m.z);
    atomicAdd(p + 3, m.w);
}

// ---------------- bond embedding ----------------
__global__ void bond_embed_kernel(const float* __restrict__ bond_float,
                                  const int*   __restrict__ bond_cat,
                                  const float* __restrict__ bond_emb,
                                  const float* __restrict__ rbfb_W,
                                  const float* __restrict__ rbfb_b) {
    int b = blockIdx.x;
    int f = threadIdx.x;
    int e2 = 2 * b;
    __shared__ float e_s[N_BCENT];
    if (f < N_BCENT) {
        float x = bond_float[e2];
        float dx = x - 0.1f * (float)f;
        e_s[f] = expf(-GAMMA * dx * dx);
    }
    __syncthreads();
    float v = rbfb_b[f];
#pragma unroll
    for (int c = 0; c < N_BCENT; c++)
        v = fmaf(e_s[c], rbfb_W[c * D + f], v);
    int c0 = bond_cat[e2 * 3 + 0];
    int c1 = bond_cat[e2 * 3 + 1];
    int c2 = bond_cat[e2 * 3 + 2];
    v += bond_emb[(0 * 16 + c0) * D + f];
    v += bond_emb[(1 * 16 + c1) * D + f];
    v += bond_emb[(2 * 16 + c2) * D + f];
    g_bond_embed[(size_t)b * D + f] = v;
}

// ---------------- lite bond-angle scatter (warp per angle) ----------------
__global__ void scatter_ba_lite_kernel(const float* __restrict__ angle_float,
                                       const int*   __restrict__ src,
                                       const int*   __restrict__ dst) {
    int a = blockIdx.x * 8 + (threadIdx.x >> 5);
    int lane = threadIdx.x & 31;
    if (a >= N_ANGLES) return;
    float x = angle_float[a];
    float dx = x - 0.1f * (float)lane;
    float e = expf(-GAMMA * dx * dx);
    int s = src[a];
    int d = dst[a];
    atomicAdd(&g_agg_e[(size_t)d * N_ACENT + lane], e);
    if (lane == 0) atomicAdd(&g_acnt[d], 1.0f);
    float4 v = reinterpret_cast<const float4*>(g_bond_embed)[(size_t)s * 32 + lane];
    float* p = &g_agg[(size_t)d * D + lane * 4];
    atomicAdd(p + 0, v.x);
    atomicAdd(p + 1, v.y);
    atomicAdd(p + 2, v.z);
    atomicAdd(p + 3, v.w);
}

// ---------------- shared helpers ----------------
#define GBM 128
#define GBK 16
#define ASTR 20
#define BSTR 136
#define HSTR 260   // h row stride (256 + 4 pad)

__device__ __forceinline__ void cp_async16(uint32_t dst, const void* src) {
    asm volatile("cp.async.cg.shared.global [%0], [%1], 16;\n"
                 :: "r"(dst), "l"(src));
}
__device__ __forceinline__ void cp_commit() { asm volatile("cp.async.commit_group;\n"); }
template<int N_> __device__ __forceinline__ void cp_wait() {
    asm volatile("cp.async.wait_group %0;\n" :: "n"(N_));
}

__device__ __forceinline__ void mma_tf32(float& c0, float& c1, float& c2, float& c3,
                                         unsigned a0, unsigned a1, unsigned a2, unsigned a3,
                                         unsigned b0, unsigned b1) {
    asm volatile(
        "mma.sync.aligned.m16n8k8.row.col.f32.tf32.tf32.f32 "
        "{%0,%1,%2,%3}, {%4,%5,%6,%7}, {%8,%9}, {%0,%1,%2,%3};\n"
        : "+f"(c0), "+f"(c1), "+f"(c2), "+f"(c3)
        : "r"(a0), "r"(a1), "r"(a2), "r"(a3), "r"(b0), "r"(b1));
}

// ---------------- expansion GEMM: C += A@B + ecnt[row]*bias ----------------
// A: MxK row-major (K=32), B: KxN row-major (N=128). Tile 128x128x16, 2 k-iters.
__global__ __launch_bounds__(256) void gemm_acc_kernel(
        const float* __restrict__ A, const float* __restrict__ B,
        const float* __restrict__ bias, float* __restrict__ C,
        const float* __restrict__ ecnt, int M, int N, int K) {
    __shared__ float As[2 * GBM * ASTR];
    __shared__ float Bs[2 * GBK * BSTR];

    int m0 = blockIdx.x * GBM;
    int tid = threadIdx.x;
    int warp = tid >> 5;
    int lane = tid & 31;
    int gidq = lane >> 2;
    int tig  = lane & 3;
    int wm = warp >> 2;
    int wn = warp & 3;

    float acc[4][4][4];
#pragma unroll
    for (int i = 0; i < 4; i++)
#pragma unroll
        for (int j = 0; j < 4; j++)
#pragma unroll
            for (int c = 0; c < 4; c++) acc[i][j][c] = 0.f;

    int a_r = tid >> 1;
    int a_c = (tid & 1) * 8;
    int b_r = tid >> 4;
    int b_c = (tid & 15) * 8;
    int a_row = m0 + a_r; if (a_row > M - 1) a_row = M - 1;
    const float* a_src_base = A + (size_t)a_row * K + a_c;
    const float* b_src_base = B + (size_t)b_r * N + b_c;

    uint32_t as_smem = (uint32_t)__cvta_generic_to_shared(As);
    uint32_t bs_smem = (uint32_t)__cvta_generic_to_shared(Bs);
    uint32_t a_dst = as_smem + (a_r * ASTR + a_c) * 4;
    uint32_t b_dst = bs_smem + (b_r * BSTR + b_c) * 4;

    const int nk = K / GBK;

    cp_async16(a_dst,      a_src_base);
    cp_async16(a_dst + 16, a_src_base + 4);
    cp_async16(b_dst,      b_src_base);
    cp_async16(b_dst + 16, b_src_base + 4);
    cp_commit();

    for (int i = 0; i < nk; i++) {
        int cur = i & 1;
        if (i + 1 < nk) {
            int nxt = cur ^ 1;
            uint32_t ad = a_dst + nxt * GBM * ASTR * 4;
            uint32_t bd = b_dst + nxt * GBK * BSTR * 4;
            const float* asrc = a_src_base + (i + 1) * GBK;
            const float* bsrc = b_src_base + (size_t)(i + 1) * GBK * N;
            cp_async16(ad,      asrc);
            cp_async16(ad + 16, asrc + 4);
            cp_async16(bd,      bsrc);
            cp_async16(bd + 16, bsrc + 4);
            cp_commit();
            cp_wait<1>();
        } else {
            cp_wait<0>();
        }
        __syncthreads();

        const float* as = As + cur * GBM * ASTR;
        const float* bs = Bs + cur * GBK * BSTR;
#pragma unroll
        for (int kk = 0; kk < GBK; kk += 8) {
            unsigned bf[4][2];
#pragma unroll
            for (int nt = 0; nt < 4; nt++) {
                int n = wn * 32 + nt * 8 + gidq;
                bf[nt][0] = __float_as_uint(bs[(kk + tig)     * BSTR + n]);
                bf[nt][1] = __float_as_uint(bs[(kk + tig + 4) * BSTR + n]);
            }
            unsigned af[4][4];
#pragma unroll
            for (int mt = 0; mt < 4; mt++) {
                int r = wm * 64 + mt * 16 + gidq;
                af[mt][0] = __float_as_uint(as[r       * ASTR + kk + tig]);
                af[mt][1] = __float_as_uint(as[(r + 8) * ASTR + kk + tig]);
                af[mt][2] = __float_as_uint(as[r       * ASTR + kk + tig + 4]);
                af[mt][3] = __float_as_uint(as[(r + 8) * ASTR + kk + tig + 4]);
            }
#pragma unroll
            for (int mt = 0; mt < 4; mt++)
#pragma unroll
                for (int nt = 0; nt < 4; nt++)
                    mma_tf32(acc[mt][nt][0], acc[mt][nt][1], acc[mt][nt][2], acc[mt][nt][3],
                             af[mt][0], af[mt][1], af[mt][2], af[mt][3],
                             bf[nt][0], bf[nt][1]);
        }
        __syncthreads();
    }

#pragma unroll
    for (int nt = 0; nt < 4; nt++) {
        int gn = wn * 32 + nt * 8 + tig * 2;
        float b0 = bias[gn], b1 = bias[gn + 1];
#pragma unroll
        for (int mt = 0; mt < 4; mt++) {
            int r0 = m0 + wm * 64 + mt * 16 + gidq;
            if (r0 < M) {
                float cc = ecnt[r0];
                float2 old = *reinterpret_cast<const float2*>(&C[(size_t)r0 * N + gn]);
                *reinterpret_cast<float2*>(&C[(size_t)r0 * N + gn]) =
                    make_float2(acc[mt][nt][0] + cc * b0 + old.x,
                                acc[mt][nt][1] + cc * b1 + old.y);
            }
            if (r0 + 8 < M) {
                float cc = ecnt[r0 + 8];
                float2 old = *reinterpret_cast<const float2*>(&C[(size_t)(r0 + 8) * N + gn]);
                *reinterpret_cast<float2*>(&C[(size_t)(r0 + 8) * N + gn]) =
                    make_float2(acc[mt][nt][2] + cc * b0 + old.x,
                                acc[mt][nt][3] + cc * b1 + old.y);
            }
        }
    }
}

// ================= fused 2-layer MLP + LN/graphnorm/relu/residual =================
// out = finish( relu(A@w1+b1) @ w2 + b2 ), A: Mx128, w1: 128x256, w2: 256x128.
// h (128x256) lives in dynamic smem; never touches gmem.
// smem layout (floats): h[0 .. 33280), As[33280 .. 38400), Bs[38400 .. 42752),
//                       s_sum[42752 .. 43264), s_sq[43264 .. 43776)
#define SM_H    0
#define SM_AS   33280
#define SM_BS   38400
#define SM_SUM  42752
#define SM_SQ   43264
#define SM_TOTF 43776
#define SM_BYTES (SM_TOTF * 4)

template<int DUP>
__global__ __launch_bounds__(256, 1) void mlp_fused_kernel(
        const float* __restrict__ A,
        const float* __restrict__ w1, const float* __restrict__ b1,
        const float* __restrict__ w2, const float* __restrict__ b2,
        float* __restrict__ C,
        const float* __restrict__ resid, const int* __restrict__ gid,
        const float* __restrict__ counts, const float* __restrict__ lng,
        const float* __restrict__ lnb, int M) {
    extern __shared__ float smem[];
    float* h_s  = smem + SM_H;
    float* As   = smem + SM_AS;
    float* Bs   = smem + SM_BS;
    float (*s_sum)[4] = reinterpret_cast<float(*)[4]>(smem + SM_SUM);
    float (*s_sq)[4]  = reinterpret_cast<float(*)[4]>(smem + SM_SQ);

    int m0 = blockIdx.x * GBM;
    int tid = threadIdx.x;
    int warp = tid >> 5;
    int lane = tid & 31;
    int gidq = lane >> 2;
    int tig  = lane & 3;
    int wm = warp >> 2;
    int wn = warp & 3;

    int a_r = tid >> 1;
    int a_c = (tid & 1) * 8;
    int b_r = tid >> 4;
    int b_c = (tid & 15) * 8;
    int a_row = m0 + a_r; if (a_row > M - 1) a_row = M - 1;
    const float* a_src_base = A + (size_t)a_row * D + a_c;

    uint32_t as_u = (uint32_t)__cvta_generic_to_shared(As);
    uint32_t bs_u = (uint32_t)__cvta_generic_to_shared(Bs);
    uint32_t a_dst = as_u + (a_r * ASTR + a_c) * 4;
    uint32_t b_dst = bs_u + (b_r * BSTR + b_c) * 4;

    float acc[4][4][4];

    // ================== PHASE 1: h = relu(A@w1 + b1), two 128-col halves ==================
#pragma unroll 1
    for (int nh = 0; nh < 2; nh++) {
#pragma unroll
        for (int i = 0; i < 4; i++)
#pragma unroll
            for (int j = 0; j < 4; j++)
#pragma unroll
                for (int c = 0; c < 4; c++) acc[i][j][c] = 0.f;

        const float* b_src_base = w1 + (size_t)b_r * H + nh * 128 + b_c;

        cp_async16(a_dst,      a_src_base);
        cp_async16(a_dst + 16, a_src_base + 4);
        cp_async16(b_dst,      b_src_base);
        cp_async16(b_dst + 16, b_src_base + 4);
        cp_commit();

        const int nk = D / GBK;   // 8
        for (int i = 0; i < nk; i++) {
            int cur = i & 1;
            if (i + 1 < nk) {
                int nxt = cur ^ 1;
                uint32_t ad = a_dst + nxt * GBM * ASTR * 4;
                uint32_t bd = b_dst + nxt * GBK * BSTR * 4;
                const float* asrc = a_src_base + (i + 1) * GBK;
                const float* bsrc = b_src_base + (size_t)(i + 1) * GBK * H;
                cp_async16(ad,      asrc);
                cp_async16(ad + 16, asrc + 4);
                cp_async16(bd,      bsrc);
                cp_async16(bd + 16, bsrc + 4);
                cp_commit();
                cp_wait<1>();
            } else {
                cp_wait<0>();
            }
            __syncthreads();

            const float* as = As + cur * GBM * ASTR;
            const float* bs = Bs + cur * GBK * BSTR;
#pragma unroll
            for (int kk = 0; kk < GBK; kk += 8) {
                unsigned bf[4][2];
#pragma unroll
                for (int nt = 0; nt < 4; nt++) {
                    int n = wn * 32 + nt * 8 + gidq;
                    bf[nt][0] = __float_as_uint(bs[(kk + tig)     * BSTR + n]);
                    bf[nt][1] = __float_as_uint(bs[(kk + tig + 4) * BSTR + n]);
                }
                unsigned af[4][4];
#pragma unroll
                for (int mt = 0; mt < 4; mt++) {
                    int r = wm * 64 + mt * 16 + gidq;
                    af[mt][0] = __float_as_uint(as[r       * ASTR + kk + tig]);
                    af[mt][1] = __float_as_uint(as[(r + 8) * ASTR + kk + tig]);
                    af[mt][2] = __float_as_uint(as[r       * ASTR + kk + tig + 4]);
                    af[mt][3] = __float_as_uint(as[(r + 8) * ASTR + kk + tig + 4]);
                }
#pragma unroll
                for (int mt = 0; mt < 4; mt++)
#pragma unroll
                    for (int nt = 0; nt < 4; nt++)
                        mma_tf32(acc[mt][nt][0], acc[mt][nt][1], acc[mt][nt][2], acc[mt][nt][3],
                                 af[mt][0], af[mt][1], af[mt][2], af[mt][3],
                                 bf[nt][0], bf[nt][1]);
            }
            __syncthreads();
        }

        // store relu(acc + b1) into h_smem half
#pragma unroll
        for (int nt = 0; nt < 4; nt++) {
            int cn = nh * 128 + wn * 32 + nt * 8 + tig * 2;
            float bb0 = b1[cn], bb1 = b1[cn + 1];
#pragma unroll
            for (int mt = 0; mt < 4; mt++) {
                int r = wm * 64 + mt * 16 + gidq;
                h_s[r * HSTR + cn]           = fmaxf(acc[mt][nt][0] + bb0, 0.f);
                h_s[r * HSTR + cn + 1]       = fmaxf(acc[mt][nt][1] + bb1, 0.f);
                h_s[(r + 8) * HSTR + cn]     = fmaxf(acc[mt][nt][2] + bb0, 0.f);
                h_s[(r + 8) * HSTR + cn + 1] = fmaxf(acc[mt][nt][3] + bb1, 0.f);
            }
        }
        __syncthreads();
    }

    // ================== PHASE 2: out = finish(h @ w2 + b2) ==================
#pragma unroll
    for (int i = 0; i < 4; i++)
#pragma unroll
        for (int j = 0; j < 4; j++)
#pragma unroll
            for (int c = 0; c < 4; c++) acc[i][j][c] = 0.f;

    {
        const float* b_src_base = w2 + (size_t)b_r * D + b_c;
        cp_async16(b_dst,      b_src_base);
        cp_async16(b_dst + 16, b_src_base + 4);
        cp_commit();

        const int nk = H / GBK;   // 16
        for (int i = 0; i < nk; i++) {
            int cur = i & 1;
            if (i + 1 < nk) {
                int nxt = cur ^ 1;
                uint32_t bd = b_dst + nxt * GBK * BSTR * 4;
                const float* bsrc = b_src_base + (size_t)(i + 1) * GBK * D;
                cp_async16(bd,      bsrc);
                cp_async16(bd + 16, bsrc + 4);
                cp_commit();
                cp_wait<1>();
            } else {
                cp_wait<0>();
            }
            __syncthreads();

            const float* bs = Bs + cur * GBK * BSTR;
            int k0 = i * GBK;
#pragma unroll
            for (int kk = 0; kk < GBK; kk += 8) {
                unsigned bf[4][2];
#pragma unroll
                for (int nt = 0; nt < 4; nt++) {
                    int n = wn * 32 + nt * 8 + gidq;
                    bf[nt][0] = __float_as_uint(bs[(kk + tig)     * BSTR + n]);
                    bf[nt][1] = __float_as_uint(bs[(kk + tig + 4) * BSTR + n]);
                }
                unsigned af[4][4];
#pragma unroll
                for (int mt = 0; mt < 4; mt++) {
                    int r = wm * 64 + mt * 16 + gidq;
                    af[mt][0] = __float_as_uint(h_s[r       * HSTR + k0 + kk + tig]);
                    af[mt][1] = __float_as_uint(h_s[(r + 8) * HSTR + k0 + kk + tig]);
                    af[mt][2] = __float_as_uint(h_s[r       * HSTR + k0 + kk + tig + 4]);
                    af[mt][3] = __float_as_uint(h_s[(r + 8) * HSTR + k0 + kk + tig + 4]);
                }
#pragma unroll
                for (int mt = 0; mt < 4; mt++)
#pragma unroll
                    for (int nt = 0; nt < 4; nt++)
                        mma_tf32(acc[mt][nt][0], acc[mt][nt][1], acc[mt][nt][2], acc[mt][nt][3],
                                 af[mt][0], af[mt][1], af[mt][2], af[mt][3],
                                 bf[nt][0], bf[nt][1]);
            }
            __syncthreads();
        }
    }

    // bias b2
#pragma unroll
    for (int nt = 0; nt < 4; nt++) {
        int gn = wn * 32 + nt * 8 + tig * 2;
        float b0 = b2[gn], b1_ = b2[gn + 1];
#pragma unroll
        for (int mt = 0; mt < 4; mt++) {
            acc[mt][nt][0] += b0; acc[mt][nt][1] += b1_;
            acc[mt][nt][2] += b0; acc[mt][nt][3] += b1_;
        }
    }

    // ---- fused LayerNorm + graphnorm + relu + residual (+dup) ----
#pragma unroll
    for (int mt = 0; mt < 4; mt++) {
        float s0 = 0.f, s1 = 0.f;
#pragma unroll
        for (int nt = 0; nt < 4; nt++) {
            s0 += acc[mt][nt][0] + acc[mt][nt][1];
            s1 += acc[mt][nt][2] + acc[mt][nt][3];
        }
        s0 += __shfl_xor_sync(0xffffffffu, s0, 1);
        s0 += __shfl_xor_sync(0xffffffffu, s0, 2);
        s1 += __shfl_xor_sync(0xffffffffu, s1, 1);
        s1 += __shfl_xor_sync(0xffffffffu, s1, 2);
        if (tig == 0) {
            int r = wm * 64 + mt * 16 + gidq;
            s_sum[r][wn] = s0;
            s_sum[r + 8][wn] = s1;
        }
    }
    __syncthreads();
    float mu[4][2];
#pragma unroll
    for (int mt = 0; mt < 4; mt++) {
        int r = wm * 64 + mt * 16 + gidq;
        mu[mt][0] = (s_sum[r][0] + s_sum[r][1] + s_sum[r][2] + s_sum[r][3]) * (1.f / 128.f);
        mu[mt][1] = (s_sum[r + 8][0] + s_sum[r + 8][1] + s_sum[r + 8][2] + s_sum[r + 8][3]) * (1.f / 128.f);
    }
#pragma unroll
    for (int mt = 0; mt < 4; mt++) {
        float q0 = 0.f, q1 = 0.f;
#pragma unroll
        for (int nt = 0; nt < 4; nt++) {
            float d0 = acc[mt][nt][0] - mu[mt][0]; q0 += d0 * d0;
            float d1 = acc[mt][nt][1] - mu[mt][0]; q0 += d1 * d1;
            float d2 = acc[mt][nt][2] - mu[mt][1]; q1 += d2 * d2;
            float d3 = acc[mt][nt][3] - mu[mt][1]; q1 += d3 * d3;
        }
        q0 += __shfl_xor_sync(0xffffffffu, q0, 1);
        q0 += __shfl_xor_sync(0xffffffffu, q0, 2);
        q1 += __shfl_xor_sync(0xffffffffu, q1, 1);
        q1 += __shfl_xor_sync(0xffffffffu, q1, 2);
        if (tig == 0) {
            int r = wm * 64 + mt * 16 + gidq;
            s_sq[r][wn] = q0;
            s_sq[r + 8][wn] = q1;
        }
    }
    __syncthreads();
    float rstd[4][2], cfac[4][2];
#pragma unroll
    for (int mt = 0; mt < 4; mt++) {
#pragma unroll
        for (int h = 0; h < 2; h++) {
            int r = wm * 64 + mt * 16 + gidq + h * 8;
            float var = (s_sq[r][0] + s_sq[r][1] + s_sq[r][2] + s_sq[r][3]) * (1.f / 128.f);
            rstd[mt][h] = rsqrtf(var + LN_EPS);
            int gr = m0 + r;
            cfac[mt][h] = (gr < M) ? rsqrtf(counts[gid[gr]]) : 0.f;
        }
    }
#pragma unroll
    for (int nt = 0; nt < 4; nt++) {
        int gn = wn * 32 + nt * 8 + tig * 2;
        float g0 = lng[gn], g1 = lng[gn + 1];
        float e0 = lnb[gn], e1 = lnb[gn + 1];
#pragma unroll
        for (int mt = 0; mt < 4; mt++) {
#pragma unroll
            for (int h = 0; h < 2; h++) {
                int r = wm * 64 + mt * 16 + gidq + h * 8;
                int gr = m0 + r;
                if (gr >= M) continue;
                float v0 = acc[mt][nt][2 * h];
                float v1 = acc[mt][nt][2 * h + 1];
                float y0 = (v0 - mu[mt][h]) * rstd[mt][h] * g0 + e0;
                float y1 = (v1 - mu[mt][h]) * rstd[mt][h] * g1 + e1;
                y0 = fmaxf(y0 * cfac[mt][h], 0.f);
                y1 = fmaxf(y1 * cfac[mt][h], 0.f);
                float2 rr = *reinterpret_cast<const float2*>(&resid[(size_t)gr * 128 + gn]);
                y0 += rr.x; y1 += rr.y;
                float2 o = make_float2(y0, y1);
                if (DUP) {
                    *reinterpret_cast<float2*>(&C[(size_t)(2 * gr)     * 128 + gn]) = o;
                    *reinterpret_cast<float2*>(&C[(size_t)(2 * gr + 1) * 128 + gn]) = o;
                } else {
                    *reinterpret_cast<float2*>(&C[(size_t)gr * 128 + gn]) = o;
                }
            }
        }
    }
}

// ---------------- host launcher ----------------
extern "C" void kernel_launch(void* const* d_in, const int* in_sizes, int n_in,
                              void* d_out, int out_size) {
    const float* node_feats  = (const float*)d_in[0];
    const float* edge_feats  = (const float*)d_in[1];
    const float* bond_float  = (const float*)d_in[2];
    const float* angle_float = (const float*)d_in[3];
    const float* bond_emb    = (const float*)d_in[4];
    const float* w1a = (const float*)d_in[5];
    const float* b1a = (const float*)d_in[6];
    const float* w2a = (const float*)d_in[7];
    const float* b2a = (const float*)d_in[8];
    const float* lng_a = (const float*)d_in[9];
    const float* lnb_a = (const float*)d_in[10];
    const float* w1b = (const float*)d_in[11];
    const float* b1b = (const float*)d_in[12];
    const float* w2b = (const float*)d_in[13];
    const float* b2b = (const float*)d_in[14];
    const float* lng_b = (const float*)d_in[15];
    const float* lnb_b = (const float*)d_in[16];
    const float* rbfb_W = (const float*)d_in[17];
    const float* rbfb_b = (const float*)d_in[18];
    const float* rbfa_W = (const float*)d_in[19];
    const float* rbfa_b = (const float*)d_in[20];
    const int* ab_src = (const int*)d_in[21];
    const int* ab_dst = (const int*)d_in[22];
    const int* ab_gid = (const int*)d_in[23];
    const int* ba_src = (const int*)d_in[24];
    const int* ba_dst = (const int*)d_in[25];
    const int* ba_gid = (const int*)d_in[26];
    const int* bond_cat = (const int*)d_in[27];

    float* out_nodes = (float*)d_out;
    float* out_edges = out_nodes + (size_t)N_ATOMS * D;

    float *agg, *bembed, *agg_e, *acnt, *cnt_a, *cnt_b;
    cudaGetSymbolAddress((void**)&agg,    g_agg);
    cudaGetSymbolAddress((void**)&bembed, g_bond_embed);
    cudaGetSymbolAddress((void**)&agg_e,  g_agg_e);
    cudaGetSymbolAddress((void**)&acnt,   g_acnt);
    cudaGetSymbolAddress((void**)&cnt_a,  g_counts_a);
    cudaGetSymbolAddress((void**)&cnt_b,  g_counts_b);

    cudaFuncSetAttribute(mlp_fused_kernel<0>,
                         cudaFuncAttributeMaxDynamicSharedMemorySize, SM_BYTES);
    cudaFuncSetAttribute(mlp_fused_kernel<1>,
                         cudaFuncAttributeMaxDynamicSharedMemorySize, SM_BYTES);

    const int zeroGrid  = (N_ATOMS * D / 4 + 255) / 256;
    const int zeroEGrid = (N_BONDS * N_ACENT / 4 + 255) / 256;
    const int mGrid = (N_ATOMS + GBM - 1) / GBM;

    // ===== graph counts =====
    zero_counts_kernel<<<(N_GRAPHS + 255) / 256, 256>>>();
    count_kernel<<<(N_ATOMS + 255) / 256, 256>>>(ab_gid, ba_gid);

    // ===== atom-bond GNN block =====
    zero_agg_kernel<<<zeroGrid, 256>>>();
    scatter_ab_kernel<<<(N_BONDS_DIR * 32 + 255) / 256, 256>>>(node_feats, edge_feats, ab_src, ab_dst);
    mlp_fused_kernel<0><<<mGrid, 256, SM_BYTES>>>(agg, w1a, b1a, w2a, b2a, out_nodes,
                                                  node_feats, ab_gid, cnt_a, lng_a, lnb_a,
                                                  N_ATOMS);

    // ===== bond-angle GNN block =====
    bond_embed_kernel<<<N_BONDS, 128>>>(bond_float, bond_cat, bond_emb, rbfb_W, rbfb_b);
    zero_agg_kernel<<<zeroGrid, 256>>>();
    zero_e_kernel<<<zeroEGrid, 256>>>();
    scatter_ba_lite_kernel<<<(N_ANGLES + 7) / 8, 256>>>(angle_float, ba_src, ba_dst);
    gemm_acc_kernel<<<mGrid, 256>>>(agg_e, rbfa_W, rbfa_b, agg, acnt, N_BONDS, D, N_ACENT);
    mlp_fused_kernel<1><<<mGrid, 256, SM_BYTES>>>(agg, w1b, b1b, w2b, b2b, out_edges,
                                                  bembed, ba_gid, cnt_b, lng_b, lnb_b,
                                                  N_BONDS);
}